// round 4
// baseline (speedup 1.0000x reference)
#include <cuda_runtime.h>
#include <math.h>

#define H      1024
#define SLEN   128
#define VOCAB  32000
#define STEPS  51
#define EOS_ID 2
#define GRID   512
#define TPB    256
#define NWARP  8
#define SIDE0  448                  // blocks [448..511] = side partition
#define NSIDE  64
#define NLOGB  448                  // blocks [0..447]  = logits partition
#define LOGW   (NLOGB * NWARP)      // 3584 logits warps
#define ROWSPW 9                    // ceil(32000/3584)

// ---------------- persistent device state ----------------
__device__ float g_hbuf[2][H];
__device__ float g_c[H];
__device__ float g_hs[SLEN * H];
__device__ float g_scores[SLEN];
__device__ float g_d[H];
__device__ float g_ht2[2][H];       // tanh-projected attention vector, double-buffered
__device__ float g_pval[2][NLOGB];  // per-block argmax partials, double-buffered
__device__ int   g_pidx[2][NLOGB];
__device__ int   g_wid;
__device__ int   g_done;
__device__ unsigned int g_bar_count;
__device__ unsigned int g_bar2;     // side-partition barrier

__global__ void k_init() {
    int t = threadIdx.x;            // 1024 threads
    g_hbuf[0][t] = 0.f;
    g_c[t] = 0.f;
    if (t == 0) { g_done = 0; g_bar_count = 0u; g_bar2 = 0u; }
}

// ---------------- barriers ----------------
__device__ __forceinline__ void gbar(unsigned int& gen) {
    __syncthreads();
    gen += GRID;
    if (threadIdx.x == 0) {
        asm volatile("fence.acq_rel.gpu;" ::: "memory");
        unsigned int prev = atomicAdd(&g_bar_count, 1u);
        if (prev + 1u != gen) {
            while (*(volatile unsigned int*)&g_bar_count < gen) { }
        }
        asm volatile("fence.acq_rel.gpu;" ::: "memory");
    }
    __syncthreads();
}

// side-partition barrier: only blocks [SIDE0..511] call this
__device__ __forceinline__ void sbar(unsigned int& gen2) {
    __syncthreads();
    gen2 += NSIDE;
    if (threadIdx.x == 0) {
        asm volatile("fence.acq_rel.gpu;" ::: "memory");
        unsigned int prev = atomicAdd(&g_bar2, 1u);
        if (prev + 1u != gen2) {
            while (*(volatile unsigned int*)&g_bar2 < gen2) { }
        }
        asm volatile("fence.acq_rel.gpu;" ::: "memory");
    }
    __syncthreads();
}

__device__ __forceinline__ float sigf(float x) { return 1.f / (1.f + expf(-x)); }
__device__ __forceinline__ float dp4(float4 a, float4 b) {
    return a.x * b.x + a.y * b.y + a.z * b.z + a.w * b.w;
}
__device__ __forceinline__ float wred(float v) {
#pragma unroll
    for (int o = 16; o; o >>= 1) v += __shfl_down_sync(0xffffffffu, v, o);
    return v;
}

// ---------------- grid-wide full LSTM (encoder / initial decode): 512 blocks, 2 units each ------
__device__ __forceinline__ void lstm_full(const float* __restrict__ Wih,
                                          const float* __restrict__ Whh,
                                          const float* __restrict__ bih,
                                          const float* __restrict__ bhh,
                                          const float* __restrict__ xrow,
                                          const float* __restrict__ hprev,
                                          float* __restrict__ hnext,
                                          float* __restrict__ hs_out, float* s_g)
{
    const int b = blockIdx.x, w = threadIdx.x >> 5, lane = threadIdx.x & 31;
    const int j = b * 2 + (w >> 2), g = w & 3;
    const float4* wi = (const float4*)(Wih + (size_t)(g * H + j) * H);
    const float4* wh = (const float4*)(Whh + (size_t)(g * H + j) * H);
    const float4* x4 = (const float4*)xrow;
    const float4* h4 = (const float4*)hprev;
    float acc = 0.f;
#pragma unroll
    for (int i = 0; i < 8; i++) acc += dp4(wi[lane + 32 * i], x4[lane + 32 * i]);
#pragma unroll
    for (int i = 0; i < 8; i++) acc += dp4(wh[lane + 32 * i], h4[lane + 32 * i]);
    acc = wred(acc);
    if (!lane) s_g[w] = acc;
    __syncthreads();
    if (threadIdx.x < 2) {
        const int jj = b * 2 + threadIdx.x;
        const int base = threadIdx.x * 4;
        float gi = s_g[base + 0] + bih[jj]         + bhh[jj];
        float gf = s_g[base + 1] + bih[H + jj]     + bhh[H + jj];
        float gg = s_g[base + 2] + bih[2 * H + jj] + bhh[2 * H + jj];
        float go = s_g[base + 3] + bih[3 * H + jj] + bhh[3 * H + jj];
        float i_ = sigf(gi), f_ = sigf(gf), g_ = tanhf(gg), o_ = sigf(go);
        float c2 = f_ * g_c[jj] + i_ * g_;
        g_c[jj] = c2;
        float hn = o_ * tanhf(c2);
        hnext[jj] = hn;
        if (hs_out) hs_out[jj] = hn;
    }
}

// ---------------- side-partition full LSTM: 64 blocks, 16 units each ----------------
__device__ __forceinline__ void lstm_side(const float* __restrict__ Wih,
                                          const float* __restrict__ Whh,
                                          const float* __restrict__ bih,
                                          const float* __restrict__ bhh,
                                          const float* __restrict__ xrow,
                                          const float* __restrict__ hprev,
                                          float* __restrict__ hnext, float* s_g)
{
    const int s = blockIdx.x - SIDE0;               // 0..63
    const int w = threadIdx.x >> 5, lane = threadIdx.x & 31;
    const int j0 = s * 16;
    const float4* x4 = (const float4*)xrow;
    const float4* h4 = (const float4*)hprev;
#pragma unroll
    for (int k = 0; k < 8; k++) {
        const int tsk = w + 8 * k;                  // 0..63
        const int jl = tsk >> 2, g = tsk & 3;
        const int j = j0 + jl;
        const float4* wi = (const float4*)(Wih + (size_t)(g * H + j) * H);
        const float4* wh = (const float4*)(Whh + (size_t)(g * H + j) * H);
        float acc = 0.f;
#pragma unroll
        for (int i = 0; i < 8; i++) acc += dp4(wi[lane + 32 * i], x4[lane + 32 * i]);
#pragma unroll
        for (int i = 0; i < 8; i++) acc += dp4(wh[lane + 32 * i], h4[lane + 32 * i]);
        acc = wred(acc);
        if (!lane) s_g[tsk] = acc;
    }
    __syncthreads();
    if (threadIdx.x < 16) {
        const int j = j0 + threadIdx.x;
        const int base = threadIdx.x * 4;
        float gi = s_g[base + 0] + bih[j]         + bhh[j];
        float gf = s_g[base + 1] + bih[H + j]     + bhh[H + j];
        float gg = s_g[base + 2] + bih[2 * H + j] + bhh[2 * H + j];
        float go = s_g[base + 3] + bih[3 * H + j] + bhh[3 * H + j];
        float i_ = sigf(gi), f_ = sigf(gf), g_ = tanhf(gg), o_ = sigf(go);
        float c2 = f_ * g_c[j] + i_ * g_;
        g_c[j] = c2;
        hnext[j] = o_ * tanhf(c2);
    }
}

// ---------------- attention scores ----------------
__device__ __forceinline__ void scores_row(int sgrid, const float* __restrict__ ht)
{
    // sgrid = global warp index among the workers; rows 0..127
    if (sgrid >= SLEN) return;
    const int lane = threadIdx.x & 31;
    const float4* r  = (const float4*)(g_hs + (size_t)sgrid * H);
    const float4* h4 = (const float4*)ht;
    float acc = 0.f;
#pragma unroll
    for (int i = 0; i < 8; i++) acc += dp4(r[lane + 32 * i], h4[lane + 32 * i]);
    acc = wred(acc);
    if (!lane) g_scores[sgrid] = acc;
}

// ---------------- softmax + context: 4 blocks, bsel = local block id 0..3 ----------------
__device__ __forceinline__ void context_piece(int bsel, float* s_sc, float* s_a, float* s_scalar)
{
    if (bsel < 0 || bsel >= 4) return;
    const int tid = threadIdx.x, w = tid >> 5, lane = tid & 31;
    if (tid < SLEN) s_sc[tid] = g_scores[tid];
    __syncthreads();
    if (w == 0) {
        float m = -INFINITY;
#pragma unroll
        for (int q = 0; q < 4; q++) m = fmaxf(m, s_sc[lane + 32 * q]);
#pragma unroll
        for (int o = 16; o; o >>= 1) m = fmaxf(m, __shfl_xor_sync(0xffffffffu, m, o));
        float sum = 0.f;
#pragma unroll
        for (int q = 0; q < 4; q++) {
            float e = expf(s_sc[lane + 32 * q] - m);
            s_a[lane + 32 * q] = e;
            sum += e;
        }
#pragma unroll
        for (int o = 16; o; o >>= 1) sum += __shfl_xor_sync(0xffffffffu, sum, o);
        if (!lane) s_scalar[0] = 1.f / sum;
    }
    __syncthreads();
    const float inv = s_scalar[0];
    const int j = bsel * TPB + tid;
    float acc = 0.f;
#pragma unroll 8
    for (int s = 0; s < SLEN; s++) acc += s_a[s] * g_hs[(size_t)s * H + j];
    g_d[j] = acc * inv;
}

// ---------------- proj row: ht2[r] = tanh(Wtl[r] @ [d;ht] + b[r]) ----------------
__device__ __forceinline__ void proj_row(int r, const float* __restrict__ Wtl,
                                         const float* __restrict__ btl,
                                         const float* __restrict__ ht,
                                         float* __restrict__ ht2out)
{
    if (r >= H) return;
    const int lane = threadIdx.x & 31;
    const float4* wr = (const float4*)(Wtl + (size_t)r * 2 * H);
    const float4* d4 = (const float4*)g_d;
    const float4* h4 = (const float4*)ht;
    float acc = 0.f;
#pragma unroll
    for (int i = 0; i < 8; i++) acc += dp4(wr[lane + 32 * i], d4[lane + 32 * i]);
#pragma unroll
    for (int i = 0; i < 8; i++) acc += dp4(wr[256 + lane + 32 * i], h4[lane + 32 * i]);
    acc = wred(acc);
    if (!lane) ht2out[r] = tanhf(acc + btl[r]);
}

// ---------------- logits GEMV on blocks [0..447], streaming, slot-buffered partials ----------------
__device__ __forceinline__ void logits_main(const float* __restrict__ W,
                                            const float* __restrict__ bias,
                                            const float* __restrict__ vec,
                                            float* __restrict__ out_logits,
                                            int slot, float* s_v, int* s_i)
{
    const int tid = threadIdx.x, w = tid >> 5, lane = tid & 31;
    const float4* x4 = (const float4*)vec;
    float4 v[8];
#pragma unroll
    for (int q = 0; q < 8; q++) v[q] = x4[lane + 32 * q];
    const int gw = blockIdx.x * NWARP + w;          // 0..3583
    float best = -INFINITY; int bidx = VOCAB;
#pragma unroll
    for (int i = 0; i < ROWSPW; i++) {
        const int r = gw + LOGW * i;                // ascending -> strict > keeps lowest idx
        if (r < VOCAB) {
            const float4* wr = (const float4*)(W + (size_t)r * H);
            float acc = 0.f;
#pragma unroll
            for (int q = 0; q < 8; q++) acc += dp4(__ldcs(wr + lane + 32 * q), v[q]);
            acc = wred(acc);
            if (!lane) {
                float lg = acc + bias[r];
                if (out_logits) __stcs(out_logits + r, lg);
                if (lg > best) { best = lg; bidx = r; }
            }
        }
    }
    if (!lane) { s_v[w] = best; s_i[w] = bidx; }
    __syncthreads();
    if (tid == 0) {
        float bv = s_v[0]; int bi = s_i[0];
#pragma unroll
        for (int q = 1; q < NWARP; q++)
            if (s_v[q] > bv || (s_v[q] == bv && s_i[q] < bi)) { bv = s_v[q]; bi = s_i[q]; }
        g_pval[slot][blockIdx.x] = bv; g_pidx[slot][blockIdx.x] = bi;
    }
}

// ---------------- final argmax + token emit (runs on one designated block) ----------------
__device__ __forceinline__ void finalize_piece(int step, int slot, float* __restrict__ out_toks,
                                               float* s_v, int* s_i)
{
    const int t = threadIdx.x;
    float bv = -INFINITY; int bi = VOCAB;
    for (int p = t; p < NLOGB; p += TPB) {
        float v = g_pval[slot][p]; int i = g_pidx[slot][p];
        if (v > bv || (v == bv && i < bi)) { bv = v; bi = i; }
    }
    s_v[t] = bv; s_i[t] = bi;
    __syncthreads();
    for (int st = 128; st > 0; st >>= 1) {
        if (t < st) {
            float v = s_v[t + st]; int i = s_i[t + st];
            if (v > s_v[t] || (v == s_v[t] && i < s_i[t])) { s_v[t] = v; s_i[t] = i; }
        }
        __syncthreads();
    }
    if (t == 0) {
        int wid = s_i[0];
        int done_prev = (step >= 0) ? g_done : 0;
        int is_eos = (wid == EOS_ID);
        if (step >= 0) out_toks[step] = (float)((done_prev || is_eos) ? -1 : wid);
        g_wid = wid;
        g_done = done_prev | is_eos;
    }
    __syncthreads();
}

// ---------------- the whole model, one persistent kernel ----------------
__global__ void __launch_bounds__(TPB, 4) k_main(
    const int* __restrict__ src,
    const float* __restrict__ embI,
    const float* __restrict__ WihE, const float* __restrict__ WhhE,
    const float* __restrict__ bihE, const float* __restrict__ bhhE,
    const float* __restrict__ Wli,  const float* __restrict__ bli,
    const float* __restrict__ embT,
    const float* __restrict__ WihD, const float* __restrict__ WhhD,
    const float* __restrict__ bihD, const float* __restrict__ bhhD,
    const float* __restrict__ Wlt,  const float* __restrict__ blt,
    const float* __restrict__ Wtl,  const float* __restrict__ btl,
    float* __restrict__ out)
{
    __shared__ float s_g[64];
    __shared__ float s_v[256];
    __shared__ int   s_i[256];
    __shared__ float s_sc[SLEN];
    __shared__ float s_a[SLEN];
    __shared__ float s_scalar[1];

    unsigned int gen = 0, gen2 = 0;
    float* out_logits = out + STEPS;
    const int b = blockIdx.x;
    const int w = threadIdx.x >> 5;

    // ---- encoder: 128 sequential full-LSTM phases (grid-wide) ----
    for (int t = 0; t < SLEN; t++) {
        lstm_full(WihE, WhhE, bihE, bhhE, embI + (size_t)src[t] * H,
                  g_hbuf[t & 1], g_hbuf[(t + 1) & 1], g_hs + (size_t)t * H, s_g);
        gbar(gen);
    }
    // final encoder h in g_hbuf[0], c in g_c

    // ---- wid0 ----
    if (b < NLOGB) logits_main(Wli, bli, g_hbuf[0], nullptr, 1, s_v, s_i);
    gbar(gen);
    if (b == SIDE0) finalize_piece(-1, 1, out, s_v, s_i);   // sets g_wid = wid0, g_done
    gbar(gen);

    // ---- initial decoder LSTM: ht(0) -> g_hbuf[1] (grid-wide) ----
    lstm_full(WihD, WhhD, bihD, bhhD, embT + (size_t)g_wid * H,
              g_hbuf[0], g_hbuf[1], nullptr, s_g);
    gbar(gen);

    // ---- scores(0), context(0), proj(0) -> g_ht2[0] (grid-wide phases) ----
    if (b >= GRID - 16) scores_row((b - (GRID - 16)) * NWARP + w, g_hbuf[1]);
    gbar(gen);
    context_piece(b < 4 ? b : -1, s_sc, s_a, s_scalar);
    gbar(gen);
    if (b < 128) {
        proj_row(b * NWARP + w, Wtl, btl, g_hbuf[1], g_ht2[0]);
    }
    gbar(gen);

    // ---- decode: 1 grid barrier per step; side chain hidden under logits stream ----
    int cur = 1;                                    // ht(t) = g_hbuf[cur]
    for (int t = 0; t < STEPS; t++) {
        if (b < NLOGB) {
            // big partition: logits(t) from ht2[t&1]
            logits_main(Wlt, blt, g_ht2[t & 1], out_logits + (size_t)t * VOCAB,
                        t & 1, s_v, s_i);
        } else {
            // side partition: finalize(t-1) -> LSTM(t) -> scores(t+1) -> context -> proj(t+1)
            const float* ht  = g_hbuf[cur];
            float*       htn = g_hbuf[1 - cur];
            const int s = b - SIDE0;                // 0..63
            if (t > 0 && s == 0) finalize_piece(t - 1, (t - 1) & 1, out, s_v, s_i);
            sbar(gen2);                             // publish g_wid
            lstm_side(WihD, WhhD, bihD, bhhD, embT + (size_t)g_wid * H, ht, htn, s_g);
            sbar(gen2);                             // publish ht(t+1)
            scores_row(s * NWARP + w, htn);
            sbar(gen2);                             // publish scores
            context_piece(s < 4 ? s : -1, s_sc, s_a, s_scalar);
            sbar(gen2);                             // publish d
            const int r0 = (s * NWARP + w) * 2;
            proj_row(r0,     Wtl, btl, htn, g_ht2[(t + 1) & 1]);
            proj_row(r0 + 1, Wtl, btl, htn, g_ht2[(t + 1) & 1]);
        }
        gbar(gen);
        cur ^= 1;
    }
    if (b == SIDE0) finalize_piece(STEPS - 1, (STEPS - 1) & 1, out, s_v, s_i);
}

// ---------------- host orchestration ----------------
extern "C" void kernel_launch(void* const* d_in, const int* in_sizes, int n_in,
                              void* d_out, int out_size)
{
    const int*   src  = (const int*)  d_in[0];
    const float* embI = (const float*)d_in[1];
    const float* WihE = (const float*)d_in[2];
    const float* WhhE = (const float*)d_in[3];
    const float* bihE = (const float*)d_in[4];
    const float* bhhE = (const float*)d_in[5];
    const float* Wli  = (const float*)d_in[6];
    const float* bli  = (const float*)d_in[7];
    const float* embT = (const float*)d_in[8];
    const float* WihD = (const float*)d_in[9];
    const float* WhhD = (const float*)d_in[10];
    const float* bihD = (const float*)d_in[11];
    const float* bhhD = (const float*)d_in[12];
    const float* Wlt  = (const float*)d_in[13];
    const float* blt  = (const float*)d_in[14];
    const float* Wtl  = (const float*)d_in[15];
    const float* btl  = (const float*)d_in[16];

    k_init<<<1, 1024>>>();
    k_main<<<GRID, TPB>>>(src, embI, WihE, WhhE, bihE, bhhE, Wli, bli, embT,
                          WihD, WhhD, bihD, bhhD, Wlt, blt, Wtl, btl,
                          (float*)d_out);
}